// round 16
// baseline (speedup 1.0000x reference)
#include <cuda_runtime.h>
#include <math.h>

#define T 4096
#define E 300
#define HID 512
#define G4 2048          // 4*HID
#define TAGS 12
#define NEGV -10000.0f
#define NB 32            // persistent blocks per direction in LSTM kernel

// ---------------- static device scratch (no allocations allowed) ----------------
__device__ float d_xg[2][T * G4];          // 2 x 32 MB: precomputed input projections
__device__ float d_Hs[2][T * HID];         // 2 x 8 MB : per-step hidden states
__device__ unsigned int d_cnt[2][T];       // per-(dir,step) arrival counters
__device__ float d_feats[T * TAGS];

// fma.rn.f32x2 (FFMA2): numerics cleared vs scalar FFMA (R3/R4 bit-identical)
#define FMA2(d, a, b, c) \
    asm("fma.rn.f32x2 %0, %1, %2, %3;" : "=l"(d) : "l"(a), "l"(b), "l"(c))

// MUFU.TANH path cleared in R10/R11 (passed, rel_err 5.7e-6)
__device__ __forceinline__ float tanh_fast(float x) {
    float r;
    asm("tanh.approx.f32 %0, %1;" : "=f"(r) : "f"(x));
    return r;
}
__device__ __forceinline__ float sigmoid_fast(float x) {
    return fmaf(tanh_fast(0.5f * x), 0.5f, 0.5f);
}

// ---------------- xg = emb[sentence] @ Wih^T + (bih + bhh), both dirs ----------------
// grid (T/32, 2048/256, 2), block 256. blockIdx.y==0 && z==0 blocks also zero
// the step counters (replaces init_kernel; same-stream ordering before lstm).
__global__ void __launch_bounds__(256) xg_kernel(
    const int*   __restrict__ sent,
    const float* __restrict__ embt,
    const float* __restrict__ Wih_f,
    const float* __restrict__ bih_f,
    const float* __restrict__ bhh_f,
    const float* __restrict__ Wih_b,
    const float* __restrict__ bih_b,
    const float* __restrict__ bhh_b)
{
    const int dir = blockIdx.z;
    const float* Wih = dir ? Wih_b : Wih_f;
    const float* bih = dir ? bih_b : bih_f;
    const float* bhh = dir ? bhh_b : bhh_f;

    // fold in counter zeroing (2*T = 8192 words over the first 32 x-blocks)
    if (blockIdx.y == 0 && blockIdx.z == 0) {
        int i = blockIdx.x * 256 + threadIdx.x;
        if (i < 2 * T) ((unsigned int*)d_cnt)[i] = 0u;
    }

    __shared__ __align__(16) float es[E * 32];   // es[k*32 + t]
    int t0 = blockIdx.x * 32;
    for (int i = threadIdx.x; i < 32 * E; i += 256) {
        int tt = i / E, k = i - tt * E;
        es[k * 32 + tt] = embt[(long long)sent[t0 + tt] * E + k];
    }
    __syncthreads();

    int r = blockIdx.y * 256 + threadIdx.x;
    const float4* w4 = (const float4*)(Wih + (long long)r * E);   // E=300 = 75 float4
    float bias = bih[r] + bhh[r];

    unsigned long long acc2[16];                  // 32 fp32 accumulators, packed
    {
        unsigned bb = __float_as_uint(bias);
        unsigned long long b2;
        asm("mov.b64 %0, {%1,%1};" : "=l"(b2) : "r"(bb));
#pragma unroll
        for (int i = 0; i < 16; i++) acc2[i] = b2;
    }

    for (int ko = 0; ko < 75; ko++) {
        float4 wq = __ldg(w4 + ko);
#pragma unroll
        for (int j = 0; j < 4; j++) {
            float wv = (j == 0) ? wq.x : (j == 1) ? wq.y : (j == 2) ? wq.z : wq.w;
            unsigned wb = __float_as_uint(wv);
            unsigned long long wvv;
            asm("mov.b64 %0, {%1,%1};" : "=l"(wvv) : "r"(wb));
            const ulonglong2* e2 = (const ulonglong2*)(es + (4 * ko + j) * 32);
#pragma unroll
            for (int q = 0; q < 8; q++) {
                ulonglong2 ev = e2[q];            // broadcast LDS.128
                FMA2(acc2[2 * q],     wvv, ev.x, acc2[2 * q]);
                FMA2(acc2[2 * q + 1], wvv, ev.y, acc2[2 * q + 1]);
            }
        }
    }

    float* xg = d_xg[dir];
#pragma unroll
    for (int i = 0; i < 16; i++) {
        float lo, hi;
        asm("mov.b64 {%0,%1}, %2;" : "=f"(lo), "=f"(hi) : "l"(acc2[i]));
        xg[(long long)(t0 + 2 * i)     * G4 + r] = lo;
        xg[(long long)(t0 + 2 * i + 1) * G4 + r] = hi;
    }
}

// ---------------- persistent BiLSTM recurrence (EXACT R14 best — frozen) ----------------
__global__ void __launch_bounds__(256, 1) lstm_kernel(
    const float* __restrict__ Whh_f,
    const float* __restrict__ Whh_b)
{
    const int bx  = blockIdx.x;
    const int dir = bx >> 5;
    const int b   = bx & 31;
    const float* Whh = dir ? Whh_b : Whh_f;
    const float* xg  = d_xg[dir];
    float* Hst = d_Hs[dir];
    unsigned int* cnt = d_cnt[dir];

    const int tid = threadIdx.x;
    const int w = tid >> 5, l = tid & 31;
    const int p  = l >> 3;                  // 0..3 row pair within warp
    const int cI = l & 7;                   // 0..7 col chunk (64 cols)
    const int lr0 = 8 * w + 2 * p;          // local gate rows
    const int lr1 = lr0 + 1;
    const int grow0 = ((lr0 >> 4) << 9) + b * 16 + (lr0 & 15);
    const int grow1 = ((lr1 >> 4) << 9) + b * 16 + (lr1 & 15);

    // weights: 2 rows x 64 cols = 128 fp32 as 64 u64 pairs, in rotated order
    unsigned long long w0reg[32], w1reg[32];
#pragma unroll
    for (int i = 0; i < 16; i++) {
        int k = (i + cI) & 15;
        ulonglong2 v0 = *(const ulonglong2*)(Whh + (long long)grow0 * HID + cI * 64 + 4 * k);
        ulonglong2 v1 = *(const ulonglong2*)(Whh + (long long)grow1 * HID + cI * 64 + 4 * k);
        w0reg[2 * i] = v0.x; w0reg[2 * i + 1] = v0.y;
        w1reg[2 * i] = v1.x; w1reg[2 * i + 1] = v1.y;
    }

    __shared__ __align__(16) float h_sh[HID];
    __shared__ __align__(8) float part_full[64];   // complete gate-row sums

    float c = 0.f;                 // cell state (warp 0 lanes 0-15)
    float xgv[4] = {0.f, 0.f, 0.f, 0.f};

    h_sh[tid] = 0.f;
    h_sh[tid + 256] = 0.f;
    if (w == 0 && l < 16) {
        int t0 = dir ? (T - 1) : 0;
#pragma unroll
        for (int g = 0; g < 4; g++)
            xgv[g] = xg[(long long)t0 * G4 + (g << 9) + b * 16 + l];
    }
    __syncthreads();

    for (int s = 0; s < T; s++) {
        const int t = dir ? (T - 1 - s) : s;

        // ---- dot: 2 rows x 64-col chunk, rotated conflict-free LDS ----
        {
            unsigned long long a00 = 0ull, a01 = 0ull, a10 = 0ull, a11 = 0ull;
            const ulonglong2* h2 = (const ulonglong2*)h_sh;
#pragma unroll
            for (int i = 0; i < 16; i++) {
                int k = (i + cI) & 15;
                ulonglong2 hv = h2[(cI << 4) + k];   // 1-phase LDS.128
                FMA2(a00, w0reg[2 * i],     hv.x, a00);
                FMA2(a01, w0reg[2 * i + 1], hv.y, a01);
                FMA2(a10, w1reg[2 * i],     hv.x, a10);
                FMA2(a11, w1reg[2 * i + 1], hv.y, a11);
            }
            float x0, x1, x2, x3, y0, y1, y2, y3;
            asm("mov.b64 {%0,%1}, %2;" : "=f"(x0), "=f"(x1) : "l"(a00));
            asm("mov.b64 {%0,%1}, %2;" : "=f"(x2), "=f"(x3) : "l"(a01));
            asm("mov.b64 {%0,%1}, %2;" : "=f"(y0), "=f"(y1) : "l"(a10));
            asm("mov.b64 {%0,%1}, %2;" : "=f"(y2), "=f"(y3) : "l"(a11));
            float s0 = (x0 + x1) + (x2 + x3);
            float s1 = (y0 + y1) + (y2 + y3);
            // width-8 pairwise reduce over the 8 col chunks
            s0 += __shfl_down_sync(0xffffffffu, s0, 4, 8);
            s1 += __shfl_down_sync(0xffffffffu, s1, 4, 8);
            s0 += __shfl_down_sync(0xffffffffu, s0, 2, 8);
            s1 += __shfl_down_sync(0xffffffffu, s1, 2, 8);
            s0 += __shfl_down_sync(0xffffffffu, s0, 1, 8);
            s1 += __shfl_down_sync(0xffffffffu, s1, 1, 8);
            if (cI == 0)
                ((float2*)part_full)[(w << 2) + p] = make_float2(s0, s1);
        }
        __syncthreads();   // A: complete row sums in smem

        if (w == 0) {
            if (l < 16) {
                float g0 = part_full[l]      + xgv[0];
                float g1 = part_full[16 + l] + xgv[1];
                float g2 = part_full[32 + l] + xgv[2];
                float g3 = part_full[48 + l] + xgv[3];

                float ig = sigmoid_fast(g0);
                float fg = sigmoid_fast(g1);
                float og = sigmoid_fast(g3);
                float tg = tanh_fast(g2);
                c = fg * c + ig * tg;
                float hh = og * tanh_fast(c);

                asm volatile("st.global.cg.f32 [%0], %1;"
                             :: "l"(Hst + (long long)t * HID + b * 16 + l),
                                "f"(hh) : "memory");

                if (s + 1 < T) {
                    int tn = dir ? (t - 1) : (t + 1);
#pragma unroll
                    for (int g = 0; g < 4; g++)
                        xgv[g] = __ldcg(xg + (long long)tn * G4 + (g << 9) + b * 16 + l);
                }
            }
            __syncwarp();   // all lanes' h stores ordered before the release
            if (l == 0) {
                asm volatile("red.release.gpu.global.add.u32 [%0], %1;"
                             :: "l"(cnt + t), "r"(1u) : "memory");
            }
        } else if (w == 1 && s + 1 < T) {
            // ---- poll ONE counter word; 2 outstanding loads per sweep ----
            unsigned v0, v1;
            do {
                asm volatile("ld.acquire.gpu.global.u32 %0, [%1];"
                             : "=r"(v0) : "l"(cnt + t) : "memory");
                asm volatile("ld.acquire.gpu.global.u32 %0, [%1];"
                             : "=r"(v1) : "l"(cnt + t) : "memory");
            } while (v0 < (unsigned)NB && v1 < (unsigned)NB);

            // ---- bulk reload h(t): 4 coalesced float4 loads per lane ----
            const float4* hp4 = (const float4*)(Hst + (long long)t * HID);
            float4 r0 = __ldcg(hp4 + l);
            float4 r1 = __ldcg(hp4 + 32 + l);
            float4 r2 = __ldcg(hp4 + 64 + l);
            float4 r3 = __ldcg(hp4 + 96 + l);
            float4* hs4 = (float4*)h_sh;
            hs4[l]      = r0;
            hs4[32 + l] = r1;
            hs4[64 + l] = r2;
            hs4[96 + l] = r3;
        }
        __syncthreads();   // B: h(t) staged in smem for next step
    }
}

// ---------------- feats = [h_f, h_b] @ W_out^T + b_out ----------------
// grid 512, block 128, 8 timesteps/block, software-pipelined h loads:
// prefetch t+1 into registers while computing t from smem.
__global__ void __launch_bounds__(128) feats_kernel(
    const float* __restrict__ W_out,
    const float* __restrict__ b_out)
{
    __shared__ __align__(16) float hb[2 * HID];
    int tid = threadIdx.x;
    int r = tid >> 3, cs = tid & 7;
    int tbase = blockIdx.x * 8;

    float4 c0 = __ldcg((const float4*)(d_Hs[0] + (long long)tbase * HID) + tid);
    float4 c1 = __ldcg((const float4*)(d_Hs[1] + (long long)tbase * HID) + tid);

    for (int tt = 0; tt < 8; tt++) {
        int t = tbase + tt;
        __syncthreads();
        ((float4*)hb)[tid]       = c0;
        ((float4*)hb)[128 + tid] = c1;
        __syncthreads();

        if (tt + 1 < 8) {   // prefetch next t (latency hidden by compute below)
            c0 = __ldcg((const float4*)(d_Hs[0] + (long long)(t + 1) * HID) + tid);
            c1 = __ldcg((const float4*)(d_Hs[1] + (long long)(t + 1) * HID) + tid);
        }

        if (tid < 96) {
            const float4* wv = (const float4*)(W_out + r * 1024 + cs * 128);
            const float4* hv = (const float4*)(hb + cs * 128);
            float s0 = 0.f, s1 = 0.f, s2 = 0.f, s3 = 0.f;
#pragma unroll
            for (int i = 0; i < 32; i++) {
                float4 a = __ldg(wv + i);
                float4 bq = hv[i];
                s0 += a.x * bq.x; s1 += a.y * bq.y;
                s2 += a.z * bq.z; s3 += a.w * bq.w;
            }
            float sum = (s0 + s1) + (s2 + s3);
#pragma unroll
            for (int o = 4; o >= 1; o >>= 1)
                sum += __shfl_down_sync(0xffffffffu, sum, o);
            if (cs == 0)
                d_feats[t * TAGS + r] = sum + b_out[r];
        }
    }
}

// ---------------- Viterbi: value-only max on the fv chain ----------------
// fv recurrence needs only the max VALUE (fmaxf tree, chain ~16cyc);
// the backpointer is recovered OFF-chain via equality mask + __ffs
// (first index attaining the max == jnp.argmax first-tie; exact since
// fmaxf returns one of its inputs bit-exactly).
__global__ void viterbi_kernel(const float* __restrict__ trans,
                               float* __restrict__ out)
{
    __shared__ unsigned long long bps[T];
    int l = threadIdx.x;

    float tr[TAGS];
    if (l < TAGS) {
#pragma unroll
        for (int pq = 0; pq < TAGS; pq++) tr[pq] = trans[l * TAGS + pq];
    } else {
#pragma unroll
        for (int pq = 0; pq < TAGS; pq++) tr[pq] = 0.f;
    }

    float fv = (l == 10) ? 0.f : NEGV;   // START = 10
    float featnext = (l < TAGS) ? d_feats[l] : 0.f;

    for (int t = 0; t < T; t++) {
        float feat = featnext;
        if (t + 1 < T && l < TAGS) featnext = d_feats[(t + 1) * TAGS + l];

        float v[TAGS];
#pragma unroll
        for (int pq = 0; pq < TAGS; pq++)
            v[pq] = __shfl_sync(0xffffffffu, fv, pq) + tr[pq];

        // value-only fmaxf tree (FMNMX, chain depth 4)
        float m01 = fmaxf(v[0], v[1]),  m23 = fmaxf(v[2], v[3]);
        float m45 = fmaxf(v[4], v[5]),  m67 = fmaxf(v[6], v[7]);
        float m89 = fmaxf(v[8], v[9]),  mab = fmaxf(v[10], v[11]);
        float q0 = fmaxf(m01, m23), q1 = fmaxf(m45, m67), q2 = fmaxf(m89, mab);
        float m = fmaxf(fmaxf(q0, q1), q2);

        fv = m + feat;                      // the only chain-critical op

        // off-chain: argmax = first index equal to the max
        unsigned msk = 0;
#pragma unroll
        for (int pq = 0; pq < TAGS; pq++)
            msk |= (v[pq] == m) ? (1u << pq) : 0u;
        int am = __ffs(msk) - 1;

        unsigned lo = (l < 8)              ? ((unsigned)am << (4 * l))       : 0u;
        unsigned hi = (l >= 8 && l < TAGS) ? ((unsigned)am << (4 * (l - 8))) : 0u;
        lo = __reduce_add_sync(0xffffffffu, lo);
        hi = __reduce_add_sync(0xffffffffu, hi);
        if (l == 0) bps[t] = ((unsigned long long)hi << 32) | lo;
    }

    float term;
    if (l < TAGS) term = fv + trans[11 * TAGS + l];
    else          term = -3.4e38f;
    if (l == 11 || l == 10) term = NEGV;

    int best = 0; float sc = -3.4e38f;
#pragma unroll
    for (int pq = 0; pq < TAGS; pq++) {
        float v2 = __shfl_sync(0xffffffffu, term, pq);
        if (v2 > sc) { sc = v2; best = pq; }
    }

    __syncwarp();

    if (l == 0) {
        out[0] = sc;
        out[T] = (float)best;            // path[T-1]
        int tag = best;
        for (int t = T - 1; t >= 1; t--) {
            int prev = (int)((bps[t] >> (4 * tag)) & 15ull);
            out[t] = (float)prev;        // path[t-1] = chain[t]
            tag = prev;
        }
    }
}

// ---------------- launch ----------------
extern "C" void kernel_launch(void* const* d_in, const int* in_sizes, int n_in,
                              void* d_out, int out_size)
{
    const int*   sent  = (const int*)d_in[0];
    const float* embt  = (const float*)d_in[1];
    const float* Wih_f = (const float*)d_in[2];
    const float* Whh_f = (const float*)d_in[3];
    const float* bih_f = (const float*)d_in[4];
    const float* bhh_f = (const float*)d_in[5];
    const float* Wih_b = (const float*)d_in[6];
    const float* Whh_b = (const float*)d_in[7];
    const float* bih_b = (const float*)d_in[8];
    const float* bhh_b = (const float*)d_in[9];
    const float* W_out = (const float*)d_in[10];
    const float* b_out = (const float*)d_in[11];
    const float* trans = (const float*)d_in[12];
    float* out = (float*)d_out;

    dim3 g(T / 32, G4 / 256, 2);
    xg_kernel<<<g, 256>>>(sent, embt, Wih_f, bih_f, bhh_f, Wih_b, bih_b, bhh_b);
    lstm_kernel<<<2 * NB, 256>>>(Whh_f, Whh_b);
    feats_kernel<<<512, 128>>>(W_out, b_out);
    viterbi_kernel<<<1, 32>>>(trans, out);
}

// round 17
// speedup vs baseline: 1.0696x; 1.0696x over previous
#include <cuda_runtime.h>
#include <math.h>

#define T 4096
#define E 300
#define HID 512
#define G4 2048          // 4*HID
#define TAGS 12
#define NEGV -10000.0f
#define NB 32            // persistent blocks per direction in LSTM kernel

// ---------------- static device scratch (no allocations allowed) ----------------
__device__ float d_xg[2][T * G4];          // 2 x 32 MB: precomputed input projections
__device__ float d_Hs[2][T * HID];         // 2 x 8 MB : per-step hidden states
__device__ unsigned int d_cnt[2][T];       // per-(dir,step) arrival counters
__device__ float d_feats[T * TAGS];

// fma.rn.f32x2 (FFMA2): numerics cleared vs scalar FFMA (R3/R4 bit-identical)
#define FMA2(d, a, b, c) \
    asm("fma.rn.f32x2 %0, %1, %2, %3;" : "=l"(d) : "l"(a), "l"(b), "l"(c))

// MUFU.TANH path cleared in R10/R11 (passed, rel_err 5.7e-6)
__device__ __forceinline__ float tanh_fast(float x) {
    float r;
    asm("tanh.approx.f32 %0, %1;" : "=f"(r) : "f"(x));
    return r;
}
__device__ __forceinline__ float sigmoid_fast(float x) {
    return fmaf(tanh_fast(0.5f * x), 0.5f, 0.5f);
}

// ---------------- zero step counters (graph replays reuse state) ----------------
__global__ void init_kernel() {
    int i = blockIdx.x * 1024 + threadIdx.x;
    if (i < 2 * T) ((unsigned int*)d_cnt)[i] = 0u;
}

// ---------------- xg = emb[sentence] @ Wih^T + (bih + bhh), both dirs ----------------
// (UNCHANGED from R12/R13/R14)
__global__ void __launch_bounds__(256) xg_kernel(
    const int*   __restrict__ sent,
    const float* __restrict__ embt,
    const float* __restrict__ Wih_f,
    const float* __restrict__ bih_f,
    const float* __restrict__ bhh_f,
    const float* __restrict__ Wih_b,
    const float* __restrict__ bih_b,
    const float* __restrict__ bhh_b)
{
    const int dir = blockIdx.z;
    const float* Wih = dir ? Wih_b : Wih_f;
    const float* bih = dir ? bih_b : bih_f;
    const float* bhh = dir ? bhh_b : bhh_f;

    __shared__ __align__(16) float es[E * 32];   // es[k*32 + t]
    int t0 = blockIdx.x * 32;
    for (int i = threadIdx.x; i < 32 * E; i += 256) {
        int tt = i / E, k = i - tt * E;
        es[k * 32 + tt] = embt[(long long)sent[t0 + tt] * E + k];
    }
    __syncthreads();

    int r = blockIdx.y * 256 + threadIdx.x;
    const float4* w4 = (const float4*)(Wih + (long long)r * E);   // E=300 = 75 float4
    float bias = bih[r] + bhh[r];

    unsigned long long acc2[16];                  // 32 fp32 accumulators, packed
    {
        unsigned bb = __float_as_uint(bias);
        unsigned long long b2;
        asm("mov.b64 %0, {%1,%1};" : "=l"(b2) : "r"(bb));
#pragma unroll
        for (int i = 0; i < 16; i++) acc2[i] = b2;
    }

    for (int ko = 0; ko < 75; ko++) {
        float4 wq = __ldg(w4 + ko);
#pragma unroll
        for (int j = 0; j < 4; j++) {
            float wv = (j == 0) ? wq.x : (j == 1) ? wq.y : (j == 2) ? wq.z : wq.w;
            unsigned wb = __float_as_uint(wv);
            unsigned long long wvv;
            asm("mov.b64 %0, {%1,%1};" : "=l"(wvv) : "r"(wb));
            const ulonglong2* e2 = (const ulonglong2*)(es + (4 * ko + j) * 32);
#pragma unroll
            for (int q = 0; q < 8; q++) {
                ulonglong2 ev = e2[q];            // broadcast LDS.128
                FMA2(acc2[2 * q],     wvv, ev.x, acc2[2 * q]);
                FMA2(acc2[2 * q + 1], wvv, ev.y, acc2[2 * q + 1]);
            }
        }
    }

    float* xg = d_xg[dir];
#pragma unroll
    for (int i = 0; i < 16; i++) {
        float lo, hi;
        asm("mov.b64 {%0,%1}, %2;" : "=f"(lo), "=f"(hi) : "l"(acc2[i]));
        xg[(long long)(t0 + 2 * i)     * G4 + r] = lo;
        xg[(long long)(t0 + 2 * i + 1) * G4 + r] = hi;
    }
}

// ---------------- persistent BiLSTM recurrence (EXACT R14 best — frozen) ----------------
__global__ void __launch_bounds__(256, 1) lstm_kernel(
    const float* __restrict__ Whh_f,
    const float* __restrict__ Whh_b)
{
    const int bx  = blockIdx.x;
    const int dir = bx >> 5;
    const int b   = bx & 31;
    const float* Whh = dir ? Whh_b : Whh_f;
    const float* xg  = d_xg[dir];
    float* Hst = d_Hs[dir];
    unsigned int* cnt = d_cnt[dir];

    const int tid = threadIdx.x;
    const int w = tid >> 5, l = tid & 31;
    const int p  = l >> 3;                  // 0..3 row pair within warp
    const int cI = l & 7;                   // 0..7 col chunk (64 cols)
    const int lr0 = 8 * w + 2 * p;          // local gate rows
    const int lr1 = lr0 + 1;
    const int grow0 = ((lr0 >> 4) << 9) + b * 16 + (lr0 & 15);
    const int grow1 = ((lr1 >> 4) << 9) + b * 16 + (lr1 & 15);

    // weights: 2 rows x 64 cols = 128 fp32 as 64 u64 pairs, in rotated order
    unsigned long long w0reg[32], w1reg[32];
#pragma unroll
    for (int i = 0; i < 16; i++) {
        int k = (i + cI) & 15;
        ulonglong2 v0 = *(const ulonglong2*)(Whh + (long long)grow0 * HID + cI * 64 + 4 * k);
        ulonglong2 v1 = *(const ulonglong2*)(Whh + (long long)grow1 * HID + cI * 64 + 4 * k);
        w0reg[2 * i] = v0.x; w0reg[2 * i + 1] = v0.y;
        w1reg[2 * i] = v1.x; w1reg[2 * i + 1] = v1.y;
    }

    __shared__ __align__(16) float h_sh[HID];
    __shared__ __align__(8) float part_full[64];   // complete gate-row sums

    float c = 0.f;                 // cell state (warp 0 lanes 0-15)
    float xgv[4] = {0.f, 0.f, 0.f, 0.f};

    h_sh[tid] = 0.f;
    h_sh[tid + 256] = 0.f;
    if (w == 0 && l < 16) {
        int t0 = dir ? (T - 1) : 0;
#pragma unroll
        for (int g = 0; g < 4; g++)
            xgv[g] = xg[(long long)t0 * G4 + (g << 9) + b * 16 + l];
    }
    __syncthreads();

    for (int s = 0; s < T; s++) {
        const int t = dir ? (T - 1 - s) : s;

        // ---- dot: 2 rows x 64-col chunk, rotated conflict-free LDS ----
        {
            unsigned long long a00 = 0ull, a01 = 0ull, a10 = 0ull, a11 = 0ull;
            const ulonglong2* h2 = (const ulonglong2*)h_sh;
#pragma unroll
            for (int i = 0; i < 16; i++) {
                int k = (i + cI) & 15;
                ulonglong2 hv = h2[(cI << 4) + k];   // 1-phase LDS.128
                FMA2(a00, w0reg[2 * i],     hv.x, a00);
                FMA2(a01, w0reg[2 * i + 1], hv.y, a01);
                FMA2(a10, w1reg[2 * i],     hv.x, a10);
                FMA2(a11, w1reg[2 * i + 1], hv.y, a11);
            }
            float x0, x1, x2, x3, y0, y1, y2, y3;
            asm("mov.b64 {%0,%1}, %2;" : "=f"(x0), "=f"(x1) : "l"(a00));
            asm("mov.b64 {%0,%1}, %2;" : "=f"(x2), "=f"(x3) : "l"(a01));
            asm("mov.b64 {%0,%1}, %2;" : "=f"(y0), "=f"(y1) : "l"(a10));
            asm("mov.b64 {%0,%1}, %2;" : "=f"(y2), "=f"(y3) : "l"(a11));
            float s0 = (x0 + x1) + (x2 + x3);
            float s1 = (y0 + y1) + (y2 + y3);
            // width-8 pairwise reduce over the 8 col chunks
            s0 += __shfl_down_sync(0xffffffffu, s0, 4, 8);
            s1 += __shfl_down_sync(0xffffffffu, s1, 4, 8);
            s0 += __shfl_down_sync(0xffffffffu, s0, 2, 8);
            s1 += __shfl_down_sync(0xffffffffu, s1, 2, 8);
            s0 += __shfl_down_sync(0xffffffffu, s0, 1, 8);
            s1 += __shfl_down_sync(0xffffffffu, s1, 1, 8);
            if (cI == 0)
                ((float2*)part_full)[(w << 2) + p] = make_float2(s0, s1);
        }
        __syncthreads();   // A: complete row sums in smem

        if (w == 0) {
            if (l < 16) {
                float g0 = part_full[l]      + xgv[0];
                float g1 = part_full[16 + l] + xgv[1];
                float g2 = part_full[32 + l] + xgv[2];
                float g3 = part_full[48 + l] + xgv[3];

                float ig = sigmoid_fast(g0);
                float fg = sigmoid_fast(g1);
                float og = sigmoid_fast(g3);
                float tg = tanh_fast(g2);
                c = fg * c + ig * tg;
                float hh = og * tanh_fast(c);

                asm volatile("st.global.cg.f32 [%0], %1;"
                             :: "l"(Hst + (long long)t * HID + b * 16 + l),
                                "f"(hh) : "memory");

                if (s + 1 < T) {
                    int tn = dir ? (t - 1) : (t + 1);
#pragma unroll
                    for (int g = 0; g < 4; g++)
                        xgv[g] = __ldcg(xg + (long long)tn * G4 + (g << 9) + b * 16 + l);
                }
            }
            __syncwarp();   // all lanes' h stores ordered before the release
            if (l == 0) {
                asm volatile("red.release.gpu.global.add.u32 [%0], %1;"
                             :: "l"(cnt + t), "r"(1u) : "memory");
            }
        } else if (w == 1 && s + 1 < T) {
            // ---- poll ONE counter word; 2 outstanding loads per sweep ----
            unsigned v0, v1;
            do {
                asm volatile("ld.acquire.gpu.global.u32 %0, [%1];"
                             : "=r"(v0) : "l"(cnt + t) : "memory");
                asm volatile("ld.acquire.gpu.global.u32 %0, [%1];"
                             : "=r"(v1) : "l"(cnt + t) : "memory");
            } while (v0 < (unsigned)NB && v1 < (unsigned)NB);

            // ---- bulk reload h(t): 4 coalesced float4 loads per lane ----
            const float4* hp4 = (const float4*)(Hst + (long long)t * HID);
            float4 r0 = __ldcg(hp4 + l);
            float4 r1 = __ldcg(hp4 + 32 + l);
            float4 r2 = __ldcg(hp4 + 64 + l);
            float4 r3 = __ldcg(hp4 + 96 + l);
            float4* hs4 = (float4*)h_sh;
            hs4[l]      = r0;
            hs4[32 + l] = r1;
            hs4[64 + l] = r2;
            hs4[96 + l] = r3;
        }
        __syncthreads();   // B: h(t) staged in smem for next step
    }
}

// ---------------- feats = [h_f, h_b] @ W_out^T + b_out ----------------
// grid 512, block 128, 8 timesteps per block. (UNCHANGED from R13/R14)
__global__ void __launch_bounds__(128) feats_kernel(
    const float* __restrict__ W_out,
    const float* __restrict__ b_out)
{
    __shared__ __align__(16) float hb[2 * HID];
    int tid = threadIdx.x;
    int r = tid >> 3, cs = tid & 7;

    for (int tt = 0; tt < 8; tt++) {
        int t = blockIdx.x * 8 + tt;
        __syncthreads();
        ((float4*)hb)[tid]       = ((const float4*)(d_Hs[0] + (long long)t * HID))[tid];
        ((float4*)hb)[128 + tid] = ((const float4*)(d_Hs[1] + (long long)t * HID))[tid];
        __syncthreads();
        if (tid < 96) {
            const float4* wv = (const float4*)(W_out + r * 1024 + cs * 128);
            const float4* hv = (const float4*)(hb + cs * 128);
            float s0 = 0.f, s1 = 0.f, s2 = 0.f, s3 = 0.f;
#pragma unroll
            for (int i = 0; i < 32; i++) {
                float4 a = __ldg(wv + i);
                float4 bq = hv[i];
                s0 += a.x * bq.x; s1 += a.y * bq.y;
                s2 += a.z * bq.z; s3 += a.w * bq.w;
            }
            float sum = (s0 + s1) + (s2 + s3);
#pragma unroll
            for (int o = 4; o >= 1; o >>= 1)
                sum += __shfl_down_sync(0xffffffffu, sum, o);
            if (cs == 0)
                d_feats[t * TAGS + r] = sum + b_out[r];
        }
    }
}

// ---------------- Viterbi: value-only max on the fv chain (ONLY change vs R14) ----
// fv recurrence needs only the max VALUE: fmaxf tree (4 FMNMX deep, ~16cyc)
// replaces the fused value+index tree (~85cyc) on the serial chain. The
// backpointer is recovered OFF-chain via equality mask + __ffs (first index
// attaining the max == jnp.argmax first-tie; exact because fmaxf returns one
// of its inputs bit-exactly, so msk != 0 always).
__global__ void viterbi_kernel(const float* __restrict__ trans,
                               float* __restrict__ out)
{
    __shared__ unsigned long long bps[T];
    int l = threadIdx.x;

    float tr[TAGS];
    if (l < TAGS) {
#pragma unroll
        for (int pq = 0; pq < TAGS; pq++) tr[pq] = trans[l * TAGS + pq];
    } else {
#pragma unroll
        for (int pq = 0; pq < TAGS; pq++) tr[pq] = 0.f;
    }

    float fv = (l == 10) ? 0.f : NEGV;   // START = 10
    float featnext = (l < TAGS) ? d_feats[l] : 0.f;

    for (int t = 0; t < T; t++) {
        float feat = featnext;
        if (t + 1 < T && l < TAGS) featnext = d_feats[(t + 1) * TAGS + l];

        float v[TAGS];
#pragma unroll
        for (int pq = 0; pq < TAGS; pq++)
            v[pq] = __shfl_sync(0xffffffffu, fv, pq) + tr[pq];

        // value-only fmaxf tree (chain depth 4)
        float m01 = fmaxf(v[0], v[1]),  m23 = fmaxf(v[2], v[3]);
        float m45 = fmaxf(v[4], v[5]),  m67 = fmaxf(v[6], v[7]);
        float m89 = fmaxf(v[8], v[9]),  mab = fmaxf(v[10], v[11]);
        float q0 = fmaxf(m01, m23), q1 = fmaxf(m45, m67), q2 = fmaxf(m89, mab);
        float m = fmaxf(fmaxf(q0, q1), q2);

        fv = m + feat;                      // the only chain-critical op

        // off-chain: argmax = first index equal to the max
        unsigned msk = 0;
#pragma unroll
        for (int pq = 0; pq < TAGS; pq++)
            msk |= (v[pq] == m) ? (1u << pq) : 0u;
        int am = __ffs(msk) - 1;

        unsigned lo = (l < 8)              ? ((unsigned)am << (4 * l))       : 0u;
        unsigned hi = (l >= 8 && l < TAGS) ? ((unsigned)am << (4 * (l - 8))) : 0u;
        lo = __reduce_add_sync(0xffffffffu, lo);
        hi = __reduce_add_sync(0xffffffffu, hi);
        if (l == 0) bps[t] = ((unsigned long long)hi << 32) | lo;
    }

    float term;
    if (l < TAGS) term = fv + trans[11 * TAGS + l];
    else          term = -3.4e38f;
    if (l == 11 || l == 10) term = NEGV;

    int best = 0; float sc = -3.4e38f;
#pragma unroll
    for (int pq = 0; pq < TAGS; pq++) {
        float v2 = __shfl_sync(0xffffffffu, term, pq);
        if (v2 > sc) { sc = v2; best = pq; }
    }

    __syncwarp();

    if (l == 0) {
        out[0] = sc;
        out[T] = (float)best;            // path[T-1]
        int tag = best;
        for (int t = T - 1; t >= 1; t--) {
            int prev = (int)((bps[t] >> (4 * tag)) & 15ull);
            out[t] = (float)prev;        // path[t-1] = chain[t]
            tag = prev;
        }
    }
}

// ---------------- launch ----------------
extern "C" void kernel_launch(void* const* d_in, const int* in_sizes, int n_in,
                              void* d_out, int out_size)
{
    const int*   sent  = (const int*)d_in[0];
    const float* embt  = (const float*)d_in[1];
    const float* Wih_f = (const float*)d_in[2];
    const float* Whh_f = (const float*)d_in[3];
    const float* bih_f = (const float*)d_in[4];
    const float* bhh_f = (const float*)d_in[5];
    const float* Wih_b = (const float*)d_in[6];
    const float* Whh_b = (const float*)d_in[7];
    const float* bih_b = (const float*)d_in[8];
    const float* bhh_b = (const float*)d_in[9];
    const float* W_out = (const float*)d_in[10];
    const float* b_out = (const float*)d_in[11];
    const float* trans = (const float*)d_in[12];
    float* out = (float*)d_out;

    init_kernel<<<8, 1024>>>();
    dim3 g(T / 32, G4 / 256, 2);
    xg_kernel<<<g, 256>>>(sent, embt, Wih_f, bih_f, bhh_f, Wih_b, bih_b, bhh_b);
    lstm_kernel<<<2 * NB, 256>>>(Whh_f, Whh_b);
    feats_kernel<<<512, 128>>>(W_out, b_out);
    viterbi_kernel<<<1, 32>>>(trans, out);
}